// round 1
// baseline (speedup 1.0000x reference)
#include <cuda_runtime.h>
#include <cuda_bf16.h>
#include <math.h>

#define D 256
#define CHUNK 96
#define NTHREADS 256

// dynamic smem layout (floats):
//   tile  [CHUNK*D]   = 24576
//   scores[CHUNK]     = 96
//   wsh   [D]         = 256
//   red   [32]        = 32
#define SMEM_FLOATS (CHUNK * D + CHUNK + D + 32)
#define SMEM_BYTES (SMEM_FLOATS * 4)

__device__ __forceinline__ int lower_bound_dev(const int* __restrict__ a, int n, int v) {
    int lo = 0, hi = n;
    while (lo < hi) {
        int mid = (lo + hi) >> 1;
        if (a[mid] < v) lo = mid + 1; else hi = mid;
    }
    return lo;
}

__device__ __forceinline__ float blk_reduce_max(float v, float* red, int tid) {
    #pragma unroll
    for (int o = 16; o; o >>= 1) v = fmaxf(v, __shfl_xor_sync(0xffffffffu, v, o));
    if ((tid & 31) == 0) red[tid >> 5] = v;
    __syncthreads();
    float r;
    if (tid < 32) {
        float t = (tid < (NTHREADS / 32)) ? red[tid] : -INFINITY;
        #pragma unroll
        for (int o = 4; o; o >>= 1) t = fmaxf(t, __shfl_xor_sync(0xffffffffu, t, o));
        if (tid == 0) red[0] = t;
    }
    __syncthreads();
    r = red[0];
    __syncthreads();   // red[] reused by next reduce
    return r;
}

__device__ __forceinline__ float blk_reduce_sum(float v, float* red, int tid) {
    #pragma unroll
    for (int o = 16; o; o >>= 1) v += __shfl_xor_sync(0xffffffffu, v, o);
    if ((tid & 31) == 0) red[tid >> 5] = v;
    __syncthreads();
    float r;
    if (tid < 32) {
        float t = (tid < (NTHREADS / 32)) ? red[tid] : 0.0f;
        #pragma unroll
        for (int o = 4; o; o >>= 1) t += __shfl_xor_sync(0xffffffffu, t, o);
        if (tid == 0) red[0] = t;
    }
    __syncthreads();
    r = red[0];
    __syncthreads();
    return r;
}

__global__ void __launch_bounds__(NTHREADS, 2)
niche_attn_kernel(const float* __restrict__ x,
                  const float* __restrict__ w,
                  const float* __restrict__ bptr,
                  const int* __restrict__ batch,
                  float* __restrict__ out,
                  int N)
{
    extern __shared__ float smem[];
    float* tile   = smem;                  // [CHUNK][D]
    float* scores = tile + CHUNK * D;      // [CHUNK]
    float* wsh    = scores + CHUNK;        // [D]
    float* red    = wsh + D;               // [32]

    __shared__ int seg_bounds[2];

    const int seg  = blockIdx.x;
    const int tid  = threadIdx.x;
    const int lane = tid & 31;
    const int warp = tid >> 5;

    // segment bounds via binary search on sorted batch
    if (tid == 0) seg_bounds[0] = lower_bound_dev(batch, N, seg);
    if (tid == 1) seg_bounds[1] = lower_bound_dev(batch, N, seg + 1);

    // stage w into smem
    wsh[tid] = w[tid];
    const float bconst = bptr[0];
    __syncthreads();

    const int start = seg_bounds[0];
    const int end   = seg_bounds[1];

    float m_run = -INFINITY;
    float s_run = 0.0f;
    float acc   = 0.0f;

    for (int base = start; base < end; base += CHUNK) {
        const int n = min(CHUNK, end - base);

        // ---- stage x[base : base+n, :] into smem (coalesced float4) ----
        {
            const float4* src = reinterpret_cast<const float4*>(x + (size_t)base * D);
            float4* dst = reinterpret_cast<float4*>(tile);
            const int total4 = n * (D / 4);
            #pragma unroll 4
            for (int i = tid; i < total4; i += NTHREADS) dst[i] = src[i];
        }
        __syncthreads();

        // ---- scores: one warp per row, dot(tile[c], w) ----
        for (int c = warp; c < n; c += NTHREADS / 32) {
            const float* row = tile + c * D;
            float p = 0.0f;
            #pragma unroll
            for (int k = 0; k < D / 32; k++)
                p = fmaf(row[lane + 32 * k], wsh[lane + 32 * k], p);
            #pragma unroll
            for (int o = 16; o; o >>= 1) p += __shfl_xor_sync(0xffffffffu, p, o);
            if (lane == 0) scores[c] = p + bconst;
        }
        __syncthreads();

        // ---- chunk max, online-softmax correction ----
        float lm = -INFINITY;
        for (int c = tid; c < n; c += NTHREADS) lm = fmaxf(lm, scores[c]);
        const float cmax  = blk_reduce_max(lm, red, tid);
        const float m_new = fmaxf(m_run, cmax);
        const float corr  = __expf(m_run - m_new);   // 0 when m_run == -inf

        // ---- exponentiate (in place) + chunk sum ----
        float ls = 0.0f;
        for (int c = tid; c < n; c += NTHREADS) {
            float e = __expf(scores[c] - m_new);
            scores[c] = e;
            ls += e;
        }
        const float csum = blk_reduce_sum(ls, red, tid);  // syncs make scores[] visible

        s_run = s_run * corr + csum;
        m_run = m_new;

        // ---- accumulate weighted rows: thread `tid` owns column `tid` ----
        float a = acc * corr;
        const float* tcol = tile + tid;
        int c = 0;
        for (; c + 3 < n; c += 4) {
            float e0 = scores[c + 0], e1 = scores[c + 1];
            float e2 = scores[c + 2], e3 = scores[c + 3];
            a = fmaf(e0, tcol[(c + 0) * D], a);
            a = fmaf(e1, tcol[(c + 1) * D], a);
            a = fmaf(e2, tcol[(c + 2) * D], a);
            a = fmaf(e3, tcol[(c + 3) * D], a);
        }
        for (; c < n; c++) a = fmaf(scores[c], tcol[c * D], a);
        acc = a;
        __syncthreads();   // protect tile/scores before next chunk overwrites
    }

    out[(size_t)seg * D + tid] = (s_run > 0.0f) ? (acc / s_run) : 0.0f;
}

extern "C" void kernel_launch(void* const* d_in, const int* in_sizes, int n_in,
                              void* d_out, int out_size)
{
    const float* x     = (const float*)d_in[0];
    const float* w     = (const float*)d_in[1];
    const float* bptr  = (const float*)d_in[2];
    const int*   batch = (const int*)d_in[3];
    // d_in[4] = num_segments scalar; B is also out_size / D

    const int N = in_sizes[3];
    const int B = out_size / D;

    cudaFuncSetAttribute(niche_attn_kernel,
                         cudaFuncAttributeMaxDynamicSharedMemorySize, SMEM_BYTES);

    niche_attn_kernel<<<B, NTHREADS, SMEM_BYTES>>>(
        x, w, bptr, batch, (float*)d_out, N);
}

// round 4
// speedup vs baseline: 2.3175x; 2.3175x over previous
#include <cuda_runtime.h>
#include <cuda_bf16.h>
#include <stdint.h>
#include <math.h>

#define D 256
#define CHUNK 24
#define NTHREADS 256
#define MAXB 4100

// dynamic smem: 2 tiles + scores + w + red
#define SMEM_FLOATS (2 * CHUNK * D + 32 + D + 8)
#define SMEM_BYTES  (SMEM_FLOATS * 4)

__device__ int g_seg_start[MAXB];

// ---- kernel 1: segment boundaries from sorted batch (parallel diff-scatter) ----
__global__ void bounds_kernel(const int* __restrict__ batch, int N, int B) {
    int i = blockIdx.x * blockDim.x + threadIdx.x;
    if (i > N) return;
    int cur  = (i < N) ? batch[i]     : B;
    int prev = (i > 0) ? batch[i - 1] : -1;
    for (int b = prev + 1; b <= cur && b <= B; b++) g_seg_start[b] = i;
}

// ---- cp.async helpers ----
__device__ __forceinline__ void cp_async16(uint32_t dst_smem, const void* src) {
    asm volatile("cp.async.cg.shared.global [%0], [%1], 16;\n" :: "r"(dst_smem), "l"(src));
}
__device__ __forceinline__ void cp_commit() {
    asm volatile("cp.async.commit_group;\n");
}
__device__ __forceinline__ void cp_wait1() {
    asm volatile("cp.async.wait_group 1;\n");
}

__device__ __forceinline__ void stage_chunk(const float* __restrict__ x, int row0,
                                            int nrows, uint32_t buf_smem, int tid) {
    const char* src = reinterpret_cast<const char*>(x + (size_t)row0 * D);
    const int total = nrows * (D / 4);      // float4 count, <= 1536
    #pragma unroll
    for (int i = tid; i < total; i += NTHREADS)
        cp_async16(buf_smem + i * 16, src + (size_t)i * 16);
}

__global__ void __launch_bounds__(NTHREADS, 4)
niche_attn_kernel(const float* __restrict__ x,
                  const float* __restrict__ w,
                  const float* __restrict__ bptr,
                  float* __restrict__ out)
{
    extern __shared__ float smem[];
    float* tile0  = smem;                       // [CHUNK][D]
    float* tile1  = tile0 + CHUNK * D;          // [CHUNK][D]
    float* scores = tile1 + CHUNK * D;          // [32]
    float* wsh    = scores + 32;                // [D]
    float* red    = wsh + D;                    // [8]

    const int seg  = blockIdx.x;
    const int tid  = threadIdx.x;
    const int lane = tid & 31;
    const int warp = tid >> 5;

    const int start = g_seg_start[seg];
    const int end   = g_seg_start[seg + 1];

    wsh[tid] = w[tid];
    const float bconst = bptr[0];

    const uint32_t buf_u32[2] = {
        (uint32_t)__cvta_generic_to_shared(tile0),
        (uint32_t)__cvta_generic_to_shared(tile1)
    };
    float* const bufs[2] = { tile0, tile1 };

    const int nch = (end - start + CHUNK - 1) / CHUNK;

    float m_run = -INFINITY;
    float s_run = 0.0f;
    float acc   = 0.0f;

    if (nch > 0)
        stage_chunk(x, start, min(CHUNK, end - start), buf_u32[0], tid);
    cp_commit();

    for (int ci = 0; ci < nch; ci++) {
        const int base = start + ci * CHUNK;
        const int n    = min(CHUNK, end - base);

        // prefetch next chunk into the other buffer
        if (ci + 1 < nch) {
            const int b2 = base + CHUNK;
            stage_chunk(x, b2, min(CHUNK, end - b2), buf_u32[(ci + 1) & 1], tid);
        }
        cp_commit();
        cp_wait1();            // chunk ci resident
        __syncthreads();       // (also covers wsh on first iter)

        const float* tile = bufs[ci & 1];

        // ---- scores: one warp per row ----
        for (int c = warp; c < n; c += NTHREADS / 32) {
            const float* row = tile + c * D;
            float p = 0.0f;
            #pragma unroll
            for (int k = 0; k < D / 32; k++)
                p = fmaf(row[lane + 32 * k], wsh[lane + 32 * k], p);
            #pragma unroll
            for (int o = 16; o; o >>= 1) p += __shfl_xor_sync(0xffffffffu, p, o);
            if (lane == 0) scores[c] = p + bconst;
        }
        __syncthreads();

        // ---- warp 0: chunk softmax (n <= 24 fits one warp) ----
        if (warp == 0) {
            float sc = (lane < n) ? scores[lane] : -INFINITY;
            float cm = sc;
            #pragma unroll
            for (int o = 16; o; o >>= 1) cm = fmaxf(cm, __shfl_xor_sync(0xffffffffu, cm, o));
            const float m_new = fmaxf(m_run, cm);
            float e = (lane < n) ? __expf(sc - m_new) : 0.0f;
            if (lane < n) scores[lane] = e;
            float cs = e;
            #pragma unroll
            for (int o = 16; o; o >>= 1) cs += __shfl_xor_sync(0xffffffffu, cs, o);
            if (lane == 0) { red[0] = cm; red[1] = cs; }
        }
        __syncthreads();

        const float m_new = fmaxf(m_run, red[0]);
        const float corr  = __expf(m_run - m_new);   // 0 when m_run == -inf
        s_run = s_run * corr + red[1];
        m_run = m_new;

        // ---- accumulate: thread owns column tid ----
        float a = acc * corr;
        const float* tcol = tile + tid;
        int c = 0;
        for (; c + 3 < n; c += 4) {
            float e0 = scores[c + 0], e1 = scores[c + 1];
            float e2 = scores[c + 2], e3 = scores[c + 3];
            a = fmaf(e0, tcol[(c + 0) * D], a);
            a = fmaf(e1, tcol[(c + 1) * D], a);
            a = fmaf(e2, tcol[(c + 2) * D], a);
            a = fmaf(e3, tcol[(c + 3) * D], a);
        }
        for (; c < n; c++) a = fmaf(scores[c], tcol[c * D], a);
        acc = a;
        __syncthreads();   // compute done before buffer is re-staged next iter
    }

    out[(size_t)seg * D + tid] = (s_run > 0.0f) ? (acc / s_run) : 0.0f;
}

extern "C" void kernel_launch(void* const* d_in, const int* in_sizes, int n_in,
                              void* d_out, int out_size)
{
    const float* x     = (const float*)d_in[0];
    const float* w     = (const float*)d_in[1];
    const float* bptr  = (const float*)d_in[2];
    const int*   batch = (const int*)d_in[3];

    const int N = in_sizes[3];
    const int B = out_size / D;

    bounds_kernel<<<(N + 1 + 255) / 256, 256>>>(batch, N, B);

    cudaFuncSetAttribute(niche_attn_kernel,
                         cudaFuncAttributeMaxDynamicSharedMemorySize, SMEM_BYTES);
    niche_attn_kernel<<<B, NTHREADS, SMEM_BYTES>>>(x, w, bptr, (float*)d_out);
}